// round 7
// baseline (speedup 1.0000x reference)
#include <cuda_runtime.h>
#include <cuda_bf16.h>
#include <cstdint>

// Problem constants
#define BB   2048
#define NAG  8
#define ACT  16
#define HIDN 64
#define TILES (BB * 2)     // M=64 tiles
#define GRID_MMA 296       // 2 CTAs per SM

// Scratch (__device__ globals: allowed)
__device__ float g_u[BB * NAG * HIDN];     // u[b,g,n]
__device__ float g_w1aT[HIDN * 128];       // w1aT[k*128 + row]

// ---------------------------------------------------------------------------
__device__ __forceinline__ uint32_t pack_hi(float a, float b) {
    uint32_t r;
    asm("prmt.b32 %0, %1, %2, 0x7632;" : "=r"(r)
        : "r"(__float_as_uint(a)), "r"(__float_as_uint(b)));
    return r;
}
__device__ __forceinline__ uint32_t pack_lo(float a, float b) {
    float ha = __uint_as_float(__float_as_uint(a) & 0xffff0000u);
    float hb = __uint_as_float(__float_as_uint(b) & 0xffff0000u);
    float la = a - ha, lb = b - hb;
    uint32_t r;
    asm("cvt.rn.bf16x2.f32 %0, %1, %2;" : "=r"(r) : "f"(lb), "f"(la));
    return r;
}
__device__ __forceinline__ uint32_t smem_u32(const void* p) {
    uint32_t a;
    asm("{ .reg .u64 t; cvta.to.shared.u64 t, %1; cvt.u32.u64 %0, t; }" : "=r"(a) : "l"(p));
    return a;
}
__device__ __forceinline__ void fma4(float4& acc, float s, const float4 w) {
    acc.x = fmaf(s, w.x, acc.x);
    acc.y = fmaf(s, w.y, acc.y);
    acc.z = fmaf(s, w.z, acc.z);
    acc.w = fmaf(s, w.w, acc.w);
}

#define LDSM_X4(r, addr) \
    asm volatile("ldmatrix.sync.aligned.m8n8.x4.shared.b16 {%0,%1,%2,%3}, [%4];" \
        : "=r"((r)[0]), "=r"((r)[1]), "=r"((r)[2]), "=r"((r)[3]) : "r"(addr))
#define LDSM_X4_T(r, addr) \
    asm volatile("ldmatrix.sync.aligned.m8n8.x4.trans.shared.b16 {%0,%1,%2,%3}, [%4];" \
        : "=r"((r)[0]), "=r"((r)[1]), "=r"((r)[2]), "=r"((r)[3]) : "r"(addr))
#define MMA16816(c, a, b0, b1) \
    asm volatile("mma.sync.aligned.m16n8k16.row.col.f32.bf16.bf16.f32 " \
        "{%0,%1,%2,%3}, {%4,%5,%6,%7}, {%8,%9}, {%0,%1,%2,%3};" \
        : "+f"((c)[0]), "+f"((c)[1]), "+f"((c)[2]), "+f"((c)[3]) \
        : "r"((a)[0]), "r"((a)[1]), "r"((a)[2]), "r"((a)[3]), "r"(b0), "r"(b1))

// ---------------------------------------------------------------------------
// Kernel 1: layer-1 factorization. 256 CTAs x 128 thr, 8 batches/CTA,
// thread = (nq in 16, bl in 8) -> one batch each (2x occupancy vs R6).
// ---------------------------------------------------------------------------
__global__ void __launch_bounds__(128) prep_kernel(
    const float* __restrict__ hidden,   // [B, 8, 32]
    const float* __restrict__ actions,  // [B, 8, 16]
    const float* __restrict__ w1,       // [384, 64]
    const float* __restrict__ b1)       // [64]
{
    __shared__ float sh[8 * 256];
    __shared__ int   sidx[64];

    const int tid = threadIdx.x;
    const int b0  = blockIdx.x * 8;
    const float4* __restrict__ w1v = reinterpret_cast<const float4*>(w1);

    if (blockIdx.x == 0) {
        // column-major action-row transpose: g_w1aT[k*128 + row]
        for (int e = tid; e < HIDN * 128; e += 128) {
            const int k   = e >> 7;
            const int row = e & 127;
            const int g   = row >> 4;
            const int a   = row & 15;
            g_w1aT[e] = __ldg(w1 + (g * 48 + 32 + a) * 64 + k);
        }
    }

    // stage hidden (8 b x 256 floats = 8 KB)
    {
        const float4* hv = reinterpret_cast<const float4*>(hidden + (size_t)b0 * 256);
        float4* shv = reinterpret_cast<float4*>(sh);
        #pragma unroll
        for (int e = tid; e < 512; e += 128) shv[e] = __ldg(hv + e);
    }

    // one-hot index per (bl, g): exact
    if (tid < 64) {
        const int bl = tid >> 3, g = tid & 7;
        const float* ag = actions + (size_t)(b0 + bl) * 128 + g * 16;
        float s = 0.f;
        #pragma unroll
        for (int a = 0; a < ACT; ++a) s = fmaf(__ldg(ag + a), (float)a, s);
        sidx[tid] = __float2int_rn(s);
    }
    __syncthreads();

    const int nq = tid & 15;
    const int bl = tid >> 4;

    float4 base = __ldg(reinterpret_cast<const float4*>(b1) + nq);
    const float* h0 = sh + bl * 256;

    #pragma unroll 2
    for (int j = 0; j < NAG; ++j) {
        #pragma unroll
        for (int i4 = 0; i4 < 8; ++i4) {
            const int wrow = j * 48 + i4 * 4;
            const float4 w0  = __ldg(w1v + (wrow + 0) * 16 + nq);
            const float4 w1_ = __ldg(w1v + (wrow + 1) * 16 + nq);
            const float4 w2_ = __ldg(w1v + (wrow + 2) * 16 + nq);
            const float4 w3_ = __ldg(w1v + (wrow + 3) * 16 + nq);
            const float4 h = *reinterpret_cast<const float4*>(h0 + j * 32 + i4 * 4);
            fma4(base, h.x, w0); fma4(base, h.y, w1_);
            fma4(base, h.z, w2_); fma4(base, h.w, w3_);
        }
    }

    float4 asum[NAG];
    float4 tot = make_float4(0.f, 0.f, 0.f, 0.f);
    #pragma unroll
    for (int g = 0; g < NAG; ++g) {
        asum[g] = __ldg(w1v + (g * 48 + 32 + sidx[bl * 8 + g]) * 16 + nq);
        tot.x += asum[g].x; tot.y += asum[g].y;
        tot.z += asum[g].z; tot.w += asum[g].w;
    }
    #pragma unroll
    for (int g = 0; g < NAG; ++g) {
        float4 v;
        v.x = base.x + tot.x - asum[g].x;
        v.y = base.y + tot.y - asum[g].y;
        v.z = base.z + tot.z - asum[g].z;
        v.w = base.w + tot.w - asum[g].w;
        *reinterpret_cast<float4*>(
            &g_u[(size_t)((b0 + bl) * NAG + g) * HIDN + nq * 4]) = v;
    }
}

// ---------------------------------------------------------------------------
// Kernel 2: persistent HMMA GEMM, M=64 tiles, B fragments register-resident.
// 256 threads (8 warps = 2 mgroups x 4 ngroups), 2 CTAs/SM, double-buffered A.
// A' = [x_hi | x_lo] chunks 0-15 (block2 aliases block0 via ks pairing),
// B' = [W_hi; W_hi; W_lo] loaded ONCE into 48 regs/warp.
// ---------------------------------------------------------------------------
#define SM_A0  0
#define SM_A1  16384
#define SM_B   32768     // 24576 bytes
#define SM_B2  57344     // b2[64]
#define SM_W3  57600     // w3[64]
#define SM_OP  57856     // opart[4][64]
#define SMEM_SZ 58880

__global__ void __launch_bounds__(256, 2) mma_kernel(
    const float* __restrict__ w2,   // [64, 64] (k-major)
    const float* __restrict__ b2,   // [64]
    const float* __restrict__ w3,   // [64]
    const float* __restrict__ b3,   // [1]
    float* __restrict__ out)        // [B, 128]
{
    extern __shared__ __align__(16) char dsm[];
    const uint32_t smAddr = smem_u32(dsm);
    float* sb2   = reinterpret_cast<float*>(dsm + SM_B2);
    float* sw3   = reinterpret_cast<float*>(dsm + SM_W3);
    float* opart = reinterpret_cast<float*>(dsm + SM_OP);

    const int tid  = threadIdx.x;
    const int wid  = tid >> 5;
    const int lane = tid & 31;

    if (tid < 64) {
        sb2[tid] = __ldg(b2 + tid);
        sw3[tid] = __ldg(w3 + tid);
    }
    const float b3v = __ldg(b3);

    // build B' = [W_hi; W_hi; W_lo] (192 k-rows x 64 n), xor-swizzled (once)
    for (int e = tid; e < 192 * 32; e += 256) {
        const int kk = e >> 5;
        const int nw = e & 31;
        const int k  = kk & 63;
        const float2 f = __ldg(reinterpret_cast<const float2*>(w2 + k * 64 + 2 * nw));
        const uint32_t word = (kk < 128) ? pack_hi(f.x, f.y) : pack_lo(f.x, f.y);
        const int nc = nw >> 2;
        const uint32_t byte = (uint32_t)kk * 128u + (uint32_t)((nc ^ (kk & 7)) << 4)
                            + (uint32_t)((nw & 3) << 2);
        *reinterpret_cast<uint32_t*>(dsm + SM_B + byte) = word;
    }
    __syncthreads();

    // lane decomposition
    const int g2  = lane >> 4;
    const int gh  = (lane >> 3) & 1;
    const int lr  = lane & 7;
    const int grp = lane >> 2;
    const int tig = lane & 3;
    const int mg  = wid >> 2;       // 0..1  (2 m-tiles each)
    const int ng  = wid & 3;        // 0..3  (2 n-tiles each)

    // B fragments -> registers, once (12 ks x 4 regs = 48 regs)
    uint32_t bfr[12][4];
    {
        const int nadd = lane >> 4;
        const uint32_t bB = smAddr + SM_B + (uint32_t)(8 * ((lane >> 3) & 1) + lr) * 128u;
        const uint32_t xr = (uint32_t)(((2 * ng + nadd) ^ lr) << 4);
        #pragma unroll
        for (int ks = 0; ks < 12; ++ks)
            LDSM_X4_T(bfr[ks], bB + (uint32_t)(ks * 2048) + xr);
    }

    // A fragment base addresses (per buffer, per m-tile)
    uint32_t aB[2][2];
    #pragma unroll
    for (int buf = 0; buf < 2; ++buf)
        #pragma unroll
        for (int mt = 0; mt < 2; ++mt)
            aB[buf][mt] = smAddr + (uint32_t)(buf * 16384)
                        + (uint32_t)(32 * mg + 16 * mt + 8 * gh + lr) * 256u;

    // build-phase decomposition: thread = (kh in 4, row in 64)
    const int kh  = tid >> 6;
    const int row = tid & 63;
    const int rx  = row & 7;
    const uint32_t rbase = (uint32_t)row * 256u;

    int it = 0;
    for (int t = blockIdx.x; t < TILES; t += GRID_MMA) {
        const int b    = t >> 1;
        const int half = t & 1;
        const int bufo = (it & 1) ? 16384 : 0;
        const int ga   = half * 64 + row;          // global (g,a) row
        const int g    = ga >> 4;

        // ---- build A' (16 k values per thread) ----
        {
            const float4* up = reinterpret_cast<const float4*>(
                g_u + (size_t)(b * NAG + g) * HIDN) + kh * 4;
            const float4 u0 = __ldg(up + 0);
            const float4 u1 = __ldg(up + 1);
            const float4 u2 = __ldg(up + 2);
            const float4 u3 = __ldg(up + 3);
            float xv[16];
            xv[0]=u0.x; xv[1]=u0.y; xv[2]=u0.z; xv[3]=u0.w;
            xv[4]=u1.x; xv[5]=u1.y; xv[6]=u1.z; xv[7]=u1.w;
            xv[8]=u2.x; xv[9]=u2.y; xv[10]=u2.z; xv[11]=u2.w;
            xv[12]=u3.x; xv[13]=u3.y; xv[14]=u3.z; xv[15]=u3.w;
            const int kb = kh * 16;
            #pragma unroll
            for (int j = 0; j < 16; ++j)
                xv[j] = fmaxf(xv[j] + __ldg(g_w1aT + (kb + j) * 128 + ga), 0.f);

            uint4 hiA, hiB, loA, loB;
            hiA.x = pack_hi(xv[0], xv[1]);  hiA.y = pack_hi(xv[2], xv[3]);
            hiA.z = pack_hi(xv[4], xv[5]);  hiA.w = pack_hi(xv[6], xv[7]);
            hiB.x = pack_hi(xv[8], xv[9]);  hiB.y = pack_hi(xv[10], xv[11]);
            hiB.z = pack_hi(xv[12], xv[13]); hiB.w = pack_hi(xv[14], xv[15]);
            loA.x = pack_lo(xv[0], xv[1]);  loA.y = pack_lo(xv[2], xv[3]);
            loA.z = pack_lo(xv[4], xv[5]);  loA.w = pack_lo(xv[6], xv[7]);
            loB.x = pack_lo(xv[8], xv[9]);  loB.y = pack_lo(xv[10], xv[11]);
            loB.z = pack_lo(xv[12], xv[13]); loB.w = pack_lo(xv[14], xv[15]);

            char* base = dsm + bufo + rbase;
            *reinterpret_cast<uint4*>(base + (((2*kh)     ^ rx) << 4)) = hiA;
            *reinterpret_cast<uint4*>(base + (((2*kh + 1) ^ rx) << 4)) = hiB;
            *reinterpret_cast<uint4*>(base + (((8 + 2*kh) ^ rx) << 4)) = loA;
            *reinterpret_cast<uint4*>(base + (((9 + 2*kh) ^ rx) << 4)) = loB;
        }
        __syncthreads();

        // ---- mma: A frags reused for ks pairs (kp, kp+8) ----
        float acc[2][2][4];
        #pragma unroll
        for (int mt = 0; mt < 2; ++mt)
            #pragma unroll
            for (int nl = 0; nl < 2; ++nl)
                #pragma unroll
                for (int q = 0; q < 4; ++q) acc[mt][nl][q] = 0.f;

        #pragma unroll
        for (int kp = 0; kp < 4; ++kp) {
            uint32_t av[2][4];
            #pragma unroll
            for (int mt = 0; mt < 2; ++mt)
                LDSM_X4(av[mt], aB[it & 1][mt] + (uint32_t)(((2*kp + g2) ^ lr) << 4));
            #pragma unroll
            for (int mt = 0; mt < 2; ++mt) {
                MMA16816(acc[mt][0], av[mt], bfr[kp][0],   bfr[kp][1]);
                MMA16816(acc[mt][1], av[mt], bfr[kp][2],   bfr[kp][3]);
                MMA16816(acc[mt][0], av[mt], bfr[kp+8][0], bfr[kp+8][1]);
                MMA16816(acc[mt][1], av[mt], bfr[kp+8][2], bfr[kp+8][3]);
            }
        }
        #pragma unroll
        for (int ks = 4; ks < 8; ++ks) {
            uint32_t av[2][4];
            #pragma unroll
            for (int mt = 0; mt < 2; ++mt)
                LDSM_X4(av[mt], aB[it & 1][mt] + (uint32_t)(((2*ks + g2) ^ lr) << 4));
            #pragma unroll
            for (int mt = 0; mt < 2; ++mt) {
                MMA16816(acc[mt][0], av[mt], bfr[ks][0], bfr[ks][1]);
                MMA16816(acc[mt][1], av[mt], bfr[ks][2], bfr[ks][3]);
            }
        }

        // ---- epilogue: +b2, relu, dot w3 over this warp's 16 cols ----
        float o[2][2] = {{0.f, 0.f}, {0.f, 0.f}};
        #pragma unroll
        for (int mt = 0; mt < 2; ++mt) {
            #pragma unroll
            for (int nl = 0; nl < 2; ++nl) {
                const int col = (2 * ng + nl) * 8 + 2 * tig;
                const float2 bb = *reinterpret_cast<const float2*>(sb2 + col);
                const float2 ww = *reinterpret_cast<const float2*>(sw3 + col);
                o[mt][0] = fmaf(fmaxf(acc[mt][nl][0] + bb.x, 0.f), ww.x, o[mt][0]);
                o[mt][0] = fmaf(fmaxf(acc[mt][nl][1] + bb.y, 0.f), ww.y, o[mt][0]);
                o[mt][1] = fmaf(fmaxf(acc[mt][nl][2] + bb.x, 0.f), ww.x, o[mt][1]);
                o[mt][1] = fmaf(fmaxf(acc[mt][nl][3] + bb.y, 0.f), ww.y, o[mt][1]);
            }
        }
        #pragma unroll
        for (int mt = 0; mt < 2; ++mt) {
            #pragma unroll
            for (int rh = 0; rh < 2; ++rh) {
                float v = o[mt][rh];
                v += __shfl_xor_sync(0xffffffffu, v, 1);
                v += __shfl_xor_sync(0xffffffffu, v, 2);
                if (tig == 0)
                    opart[ng * 64 + 32 * mg + 16 * mt + 8 * rh + grp] = v;
            }
        }
        __syncthreads();

        // cross-warp n-reduction + store
        if (tid < 64) {
            const float v = opart[tid] + opart[64 + tid]
                          + opart[128 + tid] + opart[192 + tid] + b3v;
            out[b * 128 + half * 64 + tid] = v;
        }
        ++it;
    }
}

// ---------------------------------------------------------------------------
extern "C" void kernel_launch(void* const* d_in, const int* in_sizes, int n_in,
                              void* d_out, int out_size) {
    const float* hidden  = (const float*)d_in[0];
    const float* actions = (const float*)d_in[1];
    const float* w1      = (const float*)d_in[2];
    const float* b1      = (const float*)d_in[3];
    const float* w2      = (const float*)d_in[4];
    const float* b2      = (const float*)d_in[5];
    const float* w3      = (const float*)d_in[6];
    const float* b3      = (const float*)d_in[7];
    float* out = (float*)d_out;

    cudaFuncSetAttribute(mma_kernel, cudaFuncAttributeMaxDynamicSharedMemorySize, SMEM_SZ);

    prep_kernel<<<BB / 8, 128>>>(hidden, actions, w1, b1);
    mma_kernel<<<GRID_MMA, 256, SMEM_SZ>>>(w2, b2, w3, b3, out);
}

// round 8
// speedup vs baseline: 1.1164x; 1.1164x over previous
#include <cuda_runtime.h>
#include <cuda_bf16.h>
#include <cstdint>

// Problem constants
#define BB   2048
#define NAG  8
#define ACT  16
#define HIDN 64
#define GRID_MMA 444   // 3 CTAs per SM (148 SMs)

// Scratch (__device__ globals: allowed)
__device__ float g_u[BB * NAG * HIDN];     // u[b,g,n]  (4 MB)
__device__ float g_w1aT[HIDN * 128];       // w1aT[k*128 + row]

// ---------------------------------------------------------------------------
__device__ __forceinline__ uint32_t pack_hi(float a, float b) {
    uint32_t r;
    asm("prmt.b32 %0, %1, %2, 0x7632;" : "=r"(r)
        : "r"(__float_as_uint(a)), "r"(__float_as_uint(b)));
    return r;
}
__device__ __forceinline__ uint32_t pack_lo(float a, float b) {
    float ha = __uint_as_float(__float_as_uint(a) & 0xffff0000u);
    float hb = __uint_as_float(__float_as_uint(b) & 0xffff0000u);
    float la = a - ha, lb = b - hb;
    uint32_t r;
    asm("cvt.rn.bf16x2.f32 %0, %1, %2;" : "=r"(r) : "f"(lb), "f"(la));
    return r;
}
__device__ __forceinline__ uint32_t smem_u32(const void* p) {
    uint32_t a;
    asm("{ .reg .u64 t; cvta.to.shared.u64 t, %1; cvt.u32.u64 %0, t; }" : "=r"(a) : "l"(p));
    return a;
}
__device__ __forceinline__ void fma4(float4& acc, float s, const float4 w) {
    acc.x = fmaf(s, w.x, acc.x);
    acc.y = fmaf(s, w.y, acc.y);
    acc.z = fmaf(s, w.z, acc.z);
    acc.w = fmaf(s, w.w, acc.w);
}

#define LDSM_X4(r, addr) \
    asm volatile("ldmatrix.sync.aligned.m8n8.x4.shared.b16 {%0,%1,%2,%3}, [%4];" \
        : "=r"((r)[0]), "=r"((r)[1]), "=r"((r)[2]), "=r"((r)[3]) : "r"(addr))
#define LDSM_X4_T(r, addr) \
    asm volatile("ldmatrix.sync.aligned.m8n8.x4.trans.shared.b16 {%0,%1,%2,%3}, [%4];" \
        : "=r"((r)[0]), "=r"((r)[1]), "=r"((r)[2]), "=r"((r)[3]) : "r"(addr))
#define MMA16816(c, a, b0, b1) \
    asm volatile("mma.sync.aligned.m16n8k16.row.col.f32.bf16.bf16.f32 " \
        "{%0,%1,%2,%3}, {%4,%5,%6,%7}, {%8,%9}, {%0,%1,%2,%3};" \
        : "+f"((c)[0]), "+f"((c)[1]), "+f"((c)[2]), "+f"((c)[3]) \
        : "r"((a)[0]), "r"((a)[1]), "r"((a)[2]), "r"((a)[3]), "r"(b0), "r"(b1))
#define CP_ASYNC16(dst, src) \
    asm volatile("cp.async.cg.shared.global [%0], [%1], 16;" :: "r"(dst), "l"(src) : "memory")
#define CP_COMMIT() asm volatile("cp.async.commit_group;" ::: "memory")
#define CP_WAIT0()  asm volatile("cp.async.wait_group 0;" ::: "memory")

// ---------------------------------------------------------------------------
// Kernel 1: layer-1 factorization, K-split for occupancy.
// 256 CTAs x 256 thr, 8 batches/CTA. Thread = (kq in 2, bl in 8, nq in 16):
// kq halves the 256-row hidden dot (agents kq*4..kq*4+3); partials combined
// through SMEM. One-hot actions = exact row gather.
// ---------------------------------------------------------------------------
__global__ void __launch_bounds__(256) prep_kernel(
    const float* __restrict__ hidden,   // [B, 8, 32]
    const float* __restrict__ actions,  // [B, 8, 16]
    const float* __restrict__ w1,       // [384, 64]
    const float* __restrict__ b1)       // [64]
{
    __shared__ float  sh[8 * 256];      // 8 KB staged hidden
    __shared__ float4 spart[8][16];     // 2 KB kq=1 partials
    __shared__ int    sidx[64];

    const int tid = threadIdx.x;
    const int b0  = blockIdx.x * 8;
    const float4* __restrict__ w1v = reinterpret_cast<const float4*>(w1);

    if (blockIdx.x == 0) {
        // column-major action-row transpose: g_w1aT[k*128 + row]
        for (int e = tid; e < HIDN * 128; e += 256) {
            const int k   = e >> 7;
            const int row = e & 127;
            const int g   = row >> 4;
            const int a   = row & 15;
            g_w1aT[e] = __ldg(w1 + (g * 48 + 32 + a) * 64 + k);
        }
    }

    // stage hidden (8 b x 256 floats)
    {
        const float4* hv = reinterpret_cast<const float4*>(hidden + (size_t)b0 * 256);
        float4* shv = reinterpret_cast<float4*>(sh);
        #pragma unroll
        for (int e = tid; e < 512; e += 256) shv[e] = __ldg(hv + e);
    }

    // one-hot index per (bl, g): exact
    if (tid < 64) {
        const int bl = tid >> 3, g = tid & 7;
        const float* ag = actions + (size_t)(b0 + bl) * 128 + g * 16;
        float s = 0.f;
        #pragma unroll
        for (int a = 0; a < ACT; ++a) s = fmaf(__ldg(ag + a), (float)a, s);
        sidx[tid] = __float2int_rn(s);
    }
    __syncthreads();

    const int kq = tid >> 7;
    const int bl = (tid >> 4) & 7;
    const int nq = tid & 15;

    // partial hidden dot over agents j = kq*4 .. kq*4+3
    float4 acc = make_float4(0.f, 0.f, 0.f, 0.f);
    const float* h0 = sh + bl * 256 + kq * 128;
    #pragma unroll
    for (int j2 = 0; j2 < 4; ++j2) {
        const int j = kq * 4 + j2;
        #pragma unroll
        for (int i4 = 0; i4 < 8; ++i4) {
            const int wrow = j * 48 + i4 * 4;
            const float4 w0  = __ldg(w1v + (wrow + 0) * 16 + nq);
            const float4 w1_ = __ldg(w1v + (wrow + 1) * 16 + nq);
            const float4 w2_ = __ldg(w1v + (wrow + 2) * 16 + nq);
            const float4 w3_ = __ldg(w1v + (wrow + 3) * 16 + nq);
            const float4 h = *reinterpret_cast<const float4*>(h0 + j2 * 32 + i4 * 4);
            fma4(acc, h.x, w0); fma4(acc, h.y, w1_);
            fma4(acc, h.z, w2_); fma4(acc, h.w, w3_);
        }
    }
    if (kq == 1) spart[bl][nq] = acc;
    __syncthreads();

    if (kq == 0) {
        const float4 b1v = __ldg(reinterpret_cast<const float4*>(b1) + nq);
        const float4 p = spart[bl][nq];
        float4 base;
        base.x = acc.x + p.x + b1v.x;
        base.y = acc.y + p.y + b1v.y;
        base.z = acc.z + p.z + b1v.z;
        base.w = acc.w + p.w + b1v.w;

        float4 asum[NAG];
        float4 tot = make_float4(0.f, 0.f, 0.f, 0.f);
        #pragma unroll
        for (int g = 0; g < NAG; ++g) {
            asum[g] = __ldg(w1v + (g * 48 + 32 + sidx[bl * 8 + g]) * 16 + nq);
            tot.x += asum[g].x; tot.y += asum[g].y;
            tot.z += asum[g].z; tot.w += asum[g].w;
        }
        #pragma unroll
        for (int g = 0; g < NAG; ++g) {
            float4 v;
            v.x = base.x + tot.x - asum[g].x;
            v.y = base.y + tot.y - asum[g].y;
            v.z = base.z + tot.z - asum[g].z;
            v.w = base.w + tot.w - asum[g].w;
            *reinterpret_cast<float4*>(
                &g_u[(size_t)((b0 + bl) * NAG + g) * HIDN + nq * 4]) = v;
        }
    }
}

// ---------------------------------------------------------------------------
// Kernel 2: persistent HMMA GEMM (proven R4 skeleton, 29.9us) +
// cp.async double-buffered u prefetch into SMEM (hides the tile-start
// L2 long-scoreboard; build reads become LDS broadcasts).
// A' = [x_hi | x_lo | x_hi] (block2 aliases block0), B' = [W_hi; W_hi; W_lo].
// ---------------------------------------------------------------------------
#define SM_A   0
#define SM_B   32768
#define SM_B2  57344
#define SM_W3  57600
#define SM_U   57856     // 2 x 2048-byte u slabs
#define SMEM_SZ 61952

__global__ void __launch_bounds__(128, 3) mma_kernel(
    const float* __restrict__ w2,   // [64, 64] (k-major)
    const float* __restrict__ b2,   // [64]
    const float* __restrict__ w3,   // [64]
    const float* __restrict__ b3,   // [1]
    float* __restrict__ out)        // [B, 128]
{
    extern __shared__ __align__(16) char dsm[];
    const uint32_t smAddr = smem_u32(dsm);
    const uint32_t smA = smAddr + SM_A;
    const uint32_t smB = smAddr + SM_B;
    const uint32_t smU = smAddr + SM_U;
    float* sb2 = reinterpret_cast<float*>(dsm + SM_B2);
    float* sw3 = reinterpret_cast<float*>(dsm + SM_W3);

    const int tid  = threadIdx.x;
    const int w    = tid >> 5;
    const int lane = tid & 31;

    if (tid < 64) {
        sb2[tid] = __ldg(b2 + tid);
        sw3[tid] = __ldg(w3 + tid);
    }
    const float b3v = __ldg(b3);

    // prologue: prefetch u slab for first tile into buffer 0
    CP_ASYNC16(smU + tid * 16, g_u + (size_t)blockIdx.x * 512 + tid * 4);
    CP_COMMIT();

    // build B' = [W_hi; W_hi; W_lo] (192 k-rows x 64 n), xor-swizzled
    for (int e = tid; e < 192 * 32; e += 128) {
        const int kk = e >> 5;
        const int nw = e & 31;
        const int k  = kk & 63;
        const float2 f = __ldg(reinterpret_cast<const float2*>(w2 + k * 64 + 2 * nw));
        const uint32_t word = (kk < 128) ? pack_hi(f.x, f.y) : pack_lo(f.x, f.y);
        const int nc = nw >> 2;
        const uint32_t byte = (uint32_t)kk * 128u + (uint32_t)((nc ^ (kk & 7)) << 4)
                            + (uint32_t)((nw & 3) << 2);
        *reinterpret_cast<uint32_t*>(dsm + SM_B + byte) = word;
    }

    // per-lane ldmatrix address precompute
    const int g2  = lane >> 4;
    const int gh  = (lane >> 3) & 1;
    const int lr  = lane & 7;
    const int grp = lane >> 2;
    const int tig = lane & 3;

    uint32_t aBase[2];
    #pragma unroll
    for (int mt = 0; mt < 2; ++mt)
        aBase[mt] = smA + (uint32_t)(32 * w + 16 * mt + 8 * gh + lr) * 256u;

    const int nadd = lane >> 4;
    const uint32_t bBase = smB + (uint32_t)(8 * ((lane >> 3) & 1) + lr) * 128u;
    uint32_t nxor[4];
    #pragma unroll
    for (int np = 0; np < 4; ++np)
        nxor[np] = (uint32_t)(((2 * np + nadd) ^ lr) << 4);

    const int row_ga = tid;
    const int gq     = row_ga >> 4;
    const uint32_t rbase = (uint32_t)row_ga * 256u;
    const int rx = row_ga & 7;

    int it = 0;
    for (int b = blockIdx.x; b < BB; b += GRID_MMA) {
        const int cur = it & 1;

        // u slab for this tile is in-flight: wait + make visible, and ensure
        // previous iteration's LDSM reads of A finished before overwriting.
        CP_WAIT0();
        __syncthreads();

        // build A': x1[row,k] = relu(u_s[g,k] + w1aT[k,row]); hi chunks 0-7, lo 8-15
        const float4* us = reinterpret_cast<const float4*>(dsm + SM_U + cur * 2048) + gq * 16;
        #pragma unroll
        for (int c8 = 0; c8 < 8; ++c8) {
            const int k0 = c8 * 8;
            const float4 u0 = us[c8 * 2];
            const float4 u1 = us[c8 * 2 + 1];
            float x[8];
            x[0] = u0.x; x[1] = u0.y; x[2] = u0.z; x[3] = u0.w;
            x[4] = u1.x; x[5] = u1.y; x[6] = u1.z; x[7] = u1.w;
            #pragma unroll
            for (int j = 0; j < 8; ++j)
                x[j] = fmaxf(x[j] + __ldg(g_w1aT + (k0 + j) * 128 + row_ga), 0.f);

            uint4 hi4, lo4;
            hi4.x = pack_hi(x[0], x[1]); hi4.y = pack_hi(x[2], x[3]);
            hi4.z = pack_hi(x[4], x[5]); hi4.w = pack_hi(x[6], x[7]);
            lo4.x = pack_lo(x[0], x[1]); lo4.y = pack_lo(x[2], x[3]);
            lo4.z = pack_lo(x[4], x[5]); lo4.w = pack_lo(x[6], x[7]);

            *reinterpret_cast<uint4*>(dsm + SM_A + rbase + ((c8 ^ rx) << 4))       = hi4;
            *reinterpret_cast<uint4*>(dsm + SM_A + rbase + (((8 + c8) ^ rx) << 4)) = lo4;
        }

        // prefetch u slab for the next tile into the other buffer
        {
            int bn = b + GRID_MMA;
            if (bn >= BB) bn = b;          // clamped dummy (valid memory)
            CP_ASYNC16(smU + (cur ^ 1) * 2048 + tid * 16,
                       g_u + (size_t)bn * 512 + tid * 4);
            CP_COMMIT();
        }
        __syncthreads();

        // mma phase: 12 k-steps, 2 m-tiles, 8 n-tiles
        float acc[2][8][4];
        #pragma unroll
        for (int mt = 0; mt < 2; ++mt)
            #pragma unroll
            for (int nt = 0; nt < 8; ++nt)
                #pragma unroll
                for (int q = 0; q < 4; ++q) acc[mt][nt][q] = 0.f;

        #pragma unroll
        for (int ks = 0; ks < 12; ++ks) {
            const int aks = (ks < 8) ? ks : ks - 8;      // block2 aliases block0
            uint32_t av[2][4];
            #pragma unroll
            for (int mt = 0; mt < 2; ++mt)
                LDSM_X4(av[mt], aBase[mt] + (uint32_t)(((2 * aks + g2) ^ lr) << 4));

            uint32_t bv[4][4];
            #pragma unroll
            for (int np = 0; np < 4; ++np)
                LDSM_X4_T(bv[np], bBase + (uint32_t)(ks * 2048) + nxor[np]);

            #pragma unroll
            for (int mt = 0; mt < 2; ++mt) {
                #pragma unroll
                for (int np = 0; np < 4; ++np) {
                    MMA16816(acc[mt][2 * np + 0], av[mt], bv[np][0], bv[np][1]);
                    MMA16816(acc[mt][2 * np + 1], av[mt], bv[np][2], bv[np][3]);
                }
            }
        }

        // epilogue: +b2, relu, dot w3, reduce over tig, store
        float o[2][2] = {{0.f, 0.f}, {0.f, 0.f}};
        #pragma unroll
        for (int nt = 0; nt < 8; ++nt) {
            const int col = nt * 8 + 2 * tig;
            const float2 bb = *reinterpret_cast<const float2*>(sb2 + col);
            const float2 ww = *reinterpret_cast<const float2*>(sw3 + col);
            #pragma unroll
            for (int mt = 0; mt < 2; ++mt) {
                o[mt][0] = fmaf(fmaxf(acc[mt][nt][0] + bb.x, 0.f), ww.x, o[mt][0]);
                o[mt][0] = fmaf(fmaxf(acc[mt][nt][1] + bb.y, 0.f), ww.y, o[mt][0]);
                o[mt][1] = fmaf(fmaxf(acc[mt][nt][2] + bb.x, 0.f), ww.x, o[mt][1]);
                o[mt][1] = fmaf(fmaxf(acc[mt][nt][3] + bb.y, 0.f), ww.y, o[mt][1]);
            }
        }
        #pragma unroll
        for (int mt = 0; mt < 2; ++mt) {
            #pragma unroll
            for (int rh = 0; rh < 2; ++rh) {
                float v = o[mt][rh];
                v += __shfl_xor_sync(0xffffffffu, v, 1);
                v += __shfl_xor_sync(0xffffffffu, v, 2);
                if (tig == 0) {
                    const int row = 32 * w + 16 * mt + 8 * rh + grp;
                    out[b * 128 + row] = v + b3v;
                }
            }
        }
        ++it;
    }
}

// ---------------------------------------------------------------------------
extern "C" void kernel_launch(void* const* d_in, const int* in_sizes, int n_in,
                              void* d_out, int out_size) {
    const float* hidden  = (const float*)d_in[0];
    const float* actions = (const float*)d_in[1];
    const float* w1      = (const float*)d_in[2];
    const float* b1      = (const float*)d_in[3];
    const float* w2      = (const float*)d_in[4];
    const float* b2      = (const float*)d_in[5];
    const float* w3      = (const float*)d_in[6];
    const float* b3      = (const float*)d_in[7];
    float* out = (float*)d_out;

    cudaFuncSetAttribute(mma_kernel, cudaFuncAttributeMaxDynamicSharedMemorySize, SMEM_SZ);

    prep_kernel<<<BB / 8, 256>>>(hidden, actions, w1, b1);
    mma_kernel<<<GRID_MMA, 128, SMEM_SZ>>>(w2, b2, w3, b3, out);
}

// round 9
// speedup vs baseline: 1.1174x; 1.0009x over previous
#include <cuda_runtime.h>
#include <cuda_bf16.h>
#include <cstdint>

// Problem constants
#define BB   2048
#define NAG  8
#define ACT  16
#define HIDN 64
#define GRID_MMA 444   // 3 CTAs per SM (148 SMs)

// Scratch (__device__ globals: allowed)
__device__ float g_u[BB * NAG * HIDN];     // u[b,g,n]  (4 MB)
__device__ float g_w1aT[HIDN * 128];       // w1aT[k*128 + row]

// ---------------------------------------------------------------------------
__device__ __forceinline__ uint32_t pack_hi(float a, float b) {
    uint32_t r;
    asm("prmt.b32 %0, %1, %2, 0x7632;" : "=r"(r)
        : "r"(__float_as_uint(a)), "r"(__float_as_uint(b)));
    return r;
}
__device__ __forceinline__ uint32_t pack_lo(float a, float b) {
    float ha = __uint_as_float(__float_as_uint(a) & 0xffff0000u);
    float hb = __uint_as_float(__float_as_uint(b) & 0xffff0000u);
    float la = a - ha, lb = b - hb;
    uint32_t r;
    asm("cvt.rn.bf16x2.f32 %0, %1, %2;" : "=r"(r) : "f"(lb), "f"(la));
    return r;
}
__device__ __forceinline__ uint32_t smem_u32(const void* p) {
    uint32_t a;
    asm("{ .reg .u64 t; cvta.to.shared.u64 t, %1; cvt.u32.u64 %0, t; }" : "=r"(a) : "l"(p));
    return a;
}
__device__ __forceinline__ void fma4(float4& acc, float s, const float4 w) {
    acc.x = fmaf(s, w.x, acc.x);
    acc.y = fmaf(s, w.y, acc.y);
    acc.z = fmaf(s, w.z, acc.z);
    acc.w = fmaf(s, w.w, acc.w);
}

#define LDSM_X4(r, addr) \
    asm volatile("ldmatrix.sync.aligned.m8n8.x4.shared.b16 {%0,%1,%2,%3}, [%4];" \
        : "=r"((r)[0]), "=r"((r)[1]), "=r"((r)[2]), "=r"((r)[3]) : "r"(addr))
#define LDSM_X4_T(r, addr) \
    asm volatile("ldmatrix.sync.aligned.m8n8.x4.trans.shared.b16 {%0,%1,%2,%3}, [%4];" \
        : "=r"((r)[0]), "=r"((r)[1]), "=r"((r)[2]), "=r"((r)[3]) : "r"(addr))
#define MMA16816(c, a, b0, b1) \
    asm volatile("mma.sync.aligned.m16n8k16.row.col.f32.bf16.bf16.f32 " \
        "{%0,%1,%2,%3}, {%4,%5,%6,%7}, {%8,%9}, {%0,%1,%2,%3};" \
        : "+f"((c)[0]), "+f"((c)[1]), "+f"((c)[2]), "+f"((c)[3]) \
        : "r"((a)[0]), "r"((a)[1]), "r"((a)[2]), "r"((a)[3]), "r"(b0), "r"(b1))
#define CP_ASYNC16(dst, src) \
    asm volatile("cp.async.cg.shared.global [%0], [%1], 16;" :: "r"(dst), "l"(src) : "memory")
#define CP_COMMIT() asm volatile("cp.async.commit_group;" ::: "memory")
#define CP_WAIT0()  asm volatile("cp.async.wait_group 0;" ::: "memory")

// ---------------------------------------------------------------------------
// Kernel 1: layer-1 factorization, 4-way K-split.
// 256 CTAs x 512 thr, 8 batches/CTA. Thread = (kq in 4, bl in 8, nq in 16):
// kq quarters the hidden dot (2 agents each); partials combined via SMEM.
// One-hot actions = exact row gather.
// ---------------------------------------------------------------------------
__global__ void __launch_bounds__(512) prep_kernel(
    const float* __restrict__ hidden,   // [B, 8, 32]
    const float* __restrict__ actions,  // [B, 8, 16]
    const float* __restrict__ w1,       // [384, 64]
    const float* __restrict__ b1)       // [64]
{
    __shared__ float  sh[8 * 256];        // 8 KB staged hidden
    __shared__ float4 spart[3][8][16];    // 6 KB partials (kq = 1..3)
    __shared__ int    sidx[64];

    const int tid = threadIdx.x;
    const int b0  = blockIdx.x * 8;
    const float4* __restrict__ w1v = reinterpret_cast<const float4*>(w1);

    if (blockIdx.x == 0) {
        // column-major action-row transpose: g_w1aT[k*128 + row]
        for (int e = tid; e < HIDN * 128; e += 512) {
            const int k   = e >> 7;
            const int row = e & 127;
            const int g   = row >> 4;
            const int a   = row & 15;
            g_w1aT[e] = __ldg(w1 + (g * 48 + 32 + a) * 64 + k);
        }
    }

    // stage hidden (8 b x 256 floats = 512 float4)
    if (tid < 512) {
        const float4* hv = reinterpret_cast<const float4*>(hidden + (size_t)b0 * 256);
        reinterpret_cast<float4*>(sh)[tid] = __ldg(hv + tid);
    }

    // one-hot index per (bl, g): exact
    if (tid < 64) {
        const int bl = tid >> 3, g = tid & 7;
        const float* ag = actions + (size_t)(b0 + bl) * 128 + g * 16;
        float s = 0.f;
        #pragma unroll
        for (int a = 0; a < ACT; ++a) s = fmaf(__ldg(ag + a), (float)a, s);
        sidx[tid] = __float2int_rn(s);
    }
    __syncthreads();

    const int kq = tid >> 7;          // 0..3
    const int bl = (tid >> 4) & 7;
    const int nq = tid & 15;

    // partial hidden dot over agents j = 2*kq, 2*kq+1
    float4 acc = make_float4(0.f, 0.f, 0.f, 0.f);
    const float* h0 = sh + bl * 256 + kq * 64;
    #pragma unroll
    for (int j2 = 0; j2 < 2; ++j2) {
        const int j = kq * 2 + j2;
        #pragma unroll
        for (int i4 = 0; i4 < 8; ++i4) {
            const int wrow = j * 48 + i4 * 4;
            const float4 w0  = __ldg(w1v + (wrow + 0) * 16 + nq);
            const float4 w1_ = __ldg(w1v + (wrow + 1) * 16 + nq);
            const float4 w2_ = __ldg(w1v + (wrow + 2) * 16 + nq);
            const float4 w3_ = __ldg(w1v + (wrow + 3) * 16 + nq);
            const float4 h = *reinterpret_cast<const float4*>(h0 + j2 * 32 + i4 * 4);
            fma4(acc, h.x, w0); fma4(acc, h.y, w1_);
            fma4(acc, h.z, w2_); fma4(acc, h.w, w3_);
        }
    }
    if (kq > 0) spart[kq - 1][bl][nq] = acc;
    __syncthreads();

    if (kq == 0) {
        const float4 b1v = __ldg(reinterpret_cast<const float4*>(b1) + nq);
        const float4 p0 = spart[0][bl][nq];
        const float4 p1 = spart[1][bl][nq];
        const float4 p2 = spart[2][bl][nq];
        float4 base;
        base.x = acc.x + p0.x + p1.x + p2.x + b1v.x;
        base.y = acc.y + p0.y + p1.y + p2.y + b1v.y;
        base.z = acc.z + p0.z + p1.z + p2.z + b1v.z;
        base.w = acc.w + p0.w + p1.w + p2.w + b1v.w;

        float4 asum[NAG];
        float4 tot = make_float4(0.f, 0.f, 0.f, 0.f);
        #pragma unroll
        for (int g = 0; g < NAG; ++g) {
            asum[g] = __ldg(w1v + (g * 48 + 32 + sidx[bl * 8 + g]) * 16 + nq);
            tot.x += asum[g].x; tot.y += asum[g].y;
            tot.z += asum[g].z; tot.w += asum[g].w;
        }
        #pragma unroll
        for (int g = 0; g < NAG; ++g) {
            float4 v;
            v.x = base.x + tot.x - asum[g].x;
            v.y = base.y + tot.y - asum[g].y;
            v.z = base.z + tot.z - asum[g].z;
            v.w = base.w + tot.w - asum[g].w;
            *reinterpret_cast<float4*>(
                &g_u[(size_t)((b0 + bl) * NAG + g) * HIDN + nq * 4]) = v;
        }
    }
}

// ---------------------------------------------------------------------------
// Kernel 2: persistent HMMA GEMM + cp.async u prefetch + B-dedup k-loop.
// B SMEM now stores only [W_hi; W_lo] (128 rows, 16 KB). Per physical k-chunk
// kp (0..3): load A_hi, A_lo, B_hi, B_lo once, issue all 3 split products.
// LDSM per tile: 48 (was 72). Arithmetic identical to R8.
// ---------------------------------------------------------------------------
#define SM_A   0
#define SM_B   32768     // 16384 bytes: rows 0-63 = W_hi, rows 64-127 = W_lo
#define SM_B2  49152
#define SM_W3  49408
#define SM_U   49664     // 2 x 2048-byte u slabs
#define SMEM_SZ 53760

__global__ void __launch_bounds__(128, 3) mma_kernel(
    const float* __restrict__ w2,   // [64, 64] (k-major)
    const float* __restrict__ b2,   // [64]
    const float* __restrict__ w3,   // [64]
    const float* __restrict__ b3,   // [1]
    float* __restrict__ out)        // [B, 128]
{
    extern __shared__ __align__(16) char dsm[];
    const uint32_t smAddr = smem_u32(dsm);
    const uint32_t smA = smAddr + SM_A;
    const uint32_t smB = smAddr + SM_B;
    const uint32_t smU = smAddr + SM_U;
    float* sb2 = reinterpret_cast<float*>(dsm + SM_B2);
    float* sw3 = reinterpret_cast<float*>(dsm + SM_W3);

    const int tid  = threadIdx.x;
    const int w    = tid >> 5;
    const int lane = tid & 31;

    if (tid < 64) {
        sb2[tid] = __ldg(b2 + tid);
        sw3[tid] = __ldg(w3 + tid);
    }
    const float b3v = __ldg(b3);

    // prologue: prefetch u slab for first tile into buffer 0
    CP_ASYNC16(smU + tid * 16, g_u + (size_t)blockIdx.x * 512 + tid * 4);
    CP_COMMIT();

    // build B = [W_hi; W_lo] (128 k-rows x 64 n), xor-swizzled
    for (int e = tid; e < 128 * 32; e += 128) {
        const int kk = e >> 5;
        const int nw = e & 31;
        const int k  = kk & 63;
        const float2 f = __ldg(reinterpret_cast<const float2*>(w2 + k * 64 + 2 * nw));
        const uint32_t word = (kk < 64) ? pack_hi(f.x, f.y) : pack_lo(f.x, f.y);
        const int nc = nw >> 2;
        const uint32_t byte = (uint32_t)kk * 128u + (uint32_t)((nc ^ (kk & 7)) << 4)
                            + (uint32_t)((nw & 3) << 2);
        *reinterpret_cast<uint32_t*>(dsm + SM_B + byte) = word;
    }

    // per-lane ldmatrix address precompute
    const int g2  = lane >> 4;
    const int gh  = (lane >> 3) & 1;
    const int lr  = lane & 7;
    const int grp = lane >> 2;
    const int tig = lane & 3;

    uint32_t aBase[2];
    #pragma unroll
    for (int mt = 0; mt < 2; ++mt)
        aBase[mt] = smA + (uint32_t)(32 * w + 16 * mt + 8 * gh + lr) * 256u;

    const int nadd = lane >> 4;
    const uint32_t bBase = smB + (uint32_t)(8 * ((lane >> 3) & 1) + lr) * 128u;
    uint32_t nxor[4];
    #pragma unroll
    for (int np = 0; np < 4; ++np)
        nxor[np] = (uint32_t)(((2 * np + nadd) ^ lr) << 4);

    const int row_ga = tid;
    const int gq     = row_ga >> 4;
    const uint32_t rbase = (uint32_t)row_ga * 256u;
    const int rx = row_ga & 7;

    int it = 0;
    for (int b = blockIdx.x; b < BB; b += GRID_MMA) {
        const int cur = it & 1;

        CP_WAIT0();
        __syncthreads();

        // build A': x1[row,k] = relu(u_s[g,k] + w1aT[k,row]); hi chunks 0-7, lo 8-15
        const float4* us = reinterpret_cast<const float4*>(dsm + SM_U + cur * 2048) + gq * 16;
        #pragma unroll
        for (int c8 = 0; c8 < 8; ++c8) {
            const int k0 = c8 * 8;
            const float4 u0 = us[c8 * 2];
            const float4 u1 = us[c8 * 2 + 1];
            float x[8];
            x[0] = u0.x; x[1] = u0.y; x[2] = u0.z; x[3] = u0.w;
            x[4] = u1.x; x[5] = u1.y; x[6] = u1.z; x[7] = u1.w;
            #pragma unroll
            for (int j = 0; j < 8; ++j)
                x[j] = fmaxf(x[j] + __ldg(g_w1aT + (k0 + j) * 128 + row_ga), 0.f);

            uint4 hi4, lo4;
            hi4.x = pack_hi(x[0], x[1]); hi4.y = pack_hi(x[2], x[3]);
            hi4.z = pack_hi(x[4], x[5]); hi4.w = pack_hi(x[6], x[7]);
            lo4.x = pack_lo(x[0], x[1]); lo4.y = pack_lo(x[2], x[3]);
            lo4.z = pack_lo(x[4], x[5]); lo4.w = pack_lo(x[6], x[7]);

            *reinterpret_cast<uint4*>(dsm + SM_A + rbase + ((c8 ^ rx) << 4))       = hi4;
            *reinterpret_cast<uint4*>(dsm + SM_A + rbase + (((8 + c8) ^ rx) << 4)) = lo4;
        }

        // prefetch u slab for the next tile
        {
            int bn = b + GRID_MMA;
            if (bn >= BB) bn = b;
            CP_ASYNC16(smU + (cur ^ 1) * 2048 + tid * 16,
                       g_u + (size_t)bn * 512 + tid * 4);
            CP_COMMIT();
        }
        __syncthreads();

        // mma phase: 4 physical k-chunks x 3 split products
        float acc[2][8][4];
        #pragma unroll
        for (int mt = 0; mt < 2; ++mt)
            #pragma unroll
            for (int nt = 0; nt < 8; ++nt)
                #pragma unroll
                for (int q = 0; q < 4; ++q) acc[mt][nt][q] = 0.f;

        #pragma unroll
        for (int kp = 0; kp < 4; ++kp) {
            uint32_t ah[2][4], al[2][4];
            #pragma unroll
            for (int mt = 0; mt < 2; ++mt) {
                LDSM_X4(ah[mt], aBase[mt] + (uint32_t)(((2 * kp + g2) ^ lr) << 4));
                LDSM_X4(al[mt], aBase[mt] + (uint32_t)(((8 + 2 * kp + g2) ^ lr) << 4));
            }
            uint32_t bh[4][4], blo[4][4];
            #pragma unroll
            for (int np = 0; np < 4; ++np) {
                LDSM_X4_T(bh[np],  bBase + (uint32_t)(kp * 2048)       + nxor[np]);
                LDSM_X4_T(blo[np], bBase + (uint32_t)((4 + kp) * 2048) + nxor[np]);
            }
            #pragma unroll
            for (int mt = 0; mt < 2; ++mt) {
                #pragma unroll
                for (int np = 0; np < 4; ++np) {
                    MMA16816(acc[mt][2 * np + 0], ah[mt], bh[np][0],  bh[np][1]);
                    MMA16816(acc[mt][2 * np + 1], ah[mt], bh[np][2],  bh[np][3]);
                    MMA16816(acc[mt][2 * np + 0], al[mt], bh[np][0],  bh[np][1]);
                    MMA16816(acc[mt][2 * np + 1], al[mt], bh[np][2],  bh[np][3]);
                    MMA16816(acc[mt][2 * np + 0], ah[mt], blo[np][0], blo[np][1]);
                    MMA16816(acc[mt][2 * np + 1], ah[mt], blo[np][2], blo[np][3]);
                }
            }
        }

        // epilogue: +b2, relu, dot w3, reduce over tig, store
        float o[2][2] = {{0.f, 0.f}, {0.f, 0.f}};
        #pragma unroll
        for (int nt = 0; nt < 8; ++nt) {
            const int col = nt * 8 + 2 * tig;
            const float2 bb = *reinterpret_cast<const float2*>(sb2 + col);
            const float2 ww = *reinterpret_cast<const float2*>(sw3 + col);
            #pragma unroll
            for (int mt = 0; mt < 2; ++mt) {
                o[mt][0] = fmaf(fmaxf(acc[mt][nt][0] + bb.x, 0.f), ww.x, o[mt][0]);
                o[mt][0] = fmaf(fmaxf(acc[mt][nt][1] + bb.y, 0.f), ww.y, o[mt][0]);
                o[mt][1] = fmaf(fmaxf(acc[mt][nt][2] + bb.x, 0.f), ww.x, o[mt][1]);
                o[mt][1] = fmaf(fmaxf(acc[mt][nt][3] + bb.y, 0.f), ww.y, o[mt][1]);
            }
        }
        #pragma unroll
        for (int mt = 0; mt < 2; ++mt) {
            #pragma unroll
            for (int rh = 0; rh < 2; ++rh) {
                float v = o[mt][rh];
                v += __shfl_xor_sync(0xffffffffu, v, 1);
                v += __shfl_xor_sync(0xffffffffu, v, 2);
                if (tig == 0) {
                    const int row = 32 * w + 16 * mt + 8 * rh + grp;
                    out[b * 128 + row] = v + b3v;
                }
            }
        }
        ++it;
    }
}

// ---------------------------------------------------------------------------
extern "C" void kernel_launch(void* const* d_in, const int* in_sizes, int n_in,
                              void* d_out, int out_size) {
    const float* hidden  = (const float*)d_in[0];
    const float* actions = (const float*)d_in[1];
    const float* w1      = (const float*)d_in[2];
    const float* b1      = (const float*)d_in[3];
    const float* w2      = (const float*)d_in[4];
    const float* b2      = (const float*)d_in[5];
    const float* w3      = (const float*)d_in[6];
    const float* b3      = (const float*)d_in[7];
    float* out = (float*)d_out;

    cudaFuncSetAttribute(mma_kernel, cudaFuncAttributeMaxDynamicSharedMemorySize, SMEM_SZ);

    prep_kernel<<<BB / 8, 512>>>(hidden, actions, w1, b1);
    mma_kernel<<<GRID_MMA, 128, SMEM_SZ>>>(w2, b2, w3, b3, out);
}